// round 13
// baseline (speedup 1.0000x reference)
#include <cuda_runtime.h>
#include <cuda_bf16.h>
#include <cstdint>

// ---------------------------------------------------------------------------
// Problem constants
// ---------------------------------------------------------------------------
#define Bb 8
#define Cc 256
#define NN 2304
#define EPS_BN 1e-5f
#define NSPLIT 9                 // spatial split for K@V^T (2304 / 256)

#define CH 64                    // K-chunk width (elements)
#define STG_A (128 * 128)        // A chunk bytes: 128 rows x 128B
#define STG_B (128 * 128)        // B chunk bytes: 128 rows x 128B
#define STG (STG_A + STG_B)      // 32768 per stage
#define SMEM_TOTAL (2 * STG)     // 65536 (double buffered) -> 2 CTAs/SM

#define SMEM_G3 98304            // gemm3: 2x16KB A stages + 64KB B tile

#define NT 256                   // threads per GEMM CTA (8 warps, 4x2 grid)

// ---------------------------------------------------------------------------
// Scratch (static device globals)
// ---------------------------------------------------------------------------
__device__ __nv_bfloat16 g_Xq [Bb * NN * Cc];   // Q_feat transposed [b][n][c]
__device__ __nv_bfloat16 g_Xkv[Bb * NN * Cc];   // KV_feat transposed [b][n][c]
__device__ __nv_bfloat16 g_Qt [Bb * NN * Cc];   // Q   in [b][n][o]
__device__ __nv_bfloat16 g_K  [Bb * Cc * NN];   // K   in [b][o][n]
__device__ __nv_bfloat16 g_V  [Bb * Cc * NN];   // V   in [b][o][n]
__device__ __nv_bfloat16 g_KVp[Bb * NSPLIT * Cc * Cc]; // K@V^T split partials
__device__ __nv_bfloat16 g_M  [Bb * Cc * Cc];   // Wz @ KV^T  [b][o][c]
__device__ __nv_bfloat16 g_Wqb[Cc * Cc];
__device__ __nv_bfloat16 g_Wkb[Cc * Cc];
__device__ __nv_bfloat16 g_Wvb[Cc * Cc];
__device__ __nv_bfloat16 g_Wzb[Cc * Cc];

// ---------------------------------------------------------------------------
// PTX helpers (baseline ISA only; no sm_103a-accelerated features)
// ---------------------------------------------------------------------------
__device__ __forceinline__ uint32_t s2u(const void* p) {
    uint32_t a;
    asm("{ .reg .u64 t; cvta.to.shared.u64 t, %1; cvt.u32.u64 %0, t; }"
        : "=r"(a) : "l"(p));
    return a;
}

__device__ __forceinline__ void ldsm4(uint32_t* r, uint32_t addr) {
    asm volatile(
        "ldmatrix.sync.aligned.m8n8.x4.shared.b16 {%0,%1,%2,%3}, [%4];"
        : "=r"(r[0]), "=r"(r[1]), "=r"(r[2]), "=r"(r[3]) : "r"(addr));
}

__device__ __forceinline__ void mma16816(float* d, const uint32_t* a,
                                         const uint32_t* b) {
    asm volatile(
        "mma.sync.aligned.m16n8k16.row.col.f32.bf16.bf16.f32 "
        "{%0,%1,%2,%3}, {%4,%5,%6,%7}, {%8,%9}, {%0,%1,%2,%3};"
        : "+f"(d[0]), "+f"(d[1]), "+f"(d[2]), "+f"(d[3])
        : "r"(a[0]), "r"(a[1]), "r"(a[2]), "r"(a[3]), "r"(b[0]), "r"(b[1]));
}

__device__ __forceinline__ void cp16(uint32_t dst, const void* src) {
    asm volatile("cp.async.cg.shared.global [%0], [%1], 16;"
                 :: "r"(dst), "l"(src));
}

// ---------------------------------------------------------------------------
// Async chunk loader: GMEM [128 rows x 64 bf16, row stride ld] -> swizzled
// SMEM stage. Row = 128B (8 x 16B chunks), chunk index XOR (row & 7).
// ---------------------------------------------------------------------------
__device__ __forceinline__ void load_chunk(const __nv_bfloat16* __restrict__ src,
                                           int ld, uint32_t dstu) {
    const int tid = threadIdx.x;
#pragma unroll
    for (int it = 0; it < 4; it++) {     // 128*8 chunks / 256 threads
        int idx = it * NT + tid;
        int row = idx >> 3;
        int c16 = idx & 7;
        uint32_t phys = ((uint32_t)row << 7) +
                        (((uint32_t)c16 ^ ((uint32_t)row & 7u)) << 4);
        cp16(dstu + phys, src + (size_t)row * ld + c16 * 8);
    }
}

// ---------------------------------------------------------------------------
// Compute one 64-wide k-chunk: acc[2][8][4] += A_chunk @ B_chunk^T
// 8 warps (4x2); warp (wm,wn) owns 32x64 of the 128x128 D tile.
// abase/bbase are absolute (per-warp) SMEM addresses of the A/B chunks.
// ---------------------------------------------------------------------------
__device__ __forceinline__ void compute_chunk(float acc[2][8][4],
                                              uint32_t abase, uint32_t bbase,
                                              uint32_t acol, uint32_t bcol,
                                              uint32_t xmask) {
#pragma unroll
    for (int k2 = 0; k2 < 4; k2++) {
        const uint32_t kb = (uint32_t)(k2 << 5);
        uint32_t a[2][4];
#pragma unroll
        for (int i = 0; i < 2; i++)
            ldsm4(a[i], abase + (uint32_t)(i << 11) + ((acol + kb) ^ xmask));
        uint32_t b[4][4];
#pragma unroll
        for (int jp = 0; jp < 4; jp++)
            ldsm4(b[jp], bbase + (uint32_t)(jp << 11) + ((bcol + kb) ^ xmask));
#pragma unroll
        for (int i = 0; i < 2; i++)
#pragma unroll
            for (int j = 0; j < 8; j++)
                mma16816(acc[i][j], a[i], &b[j >> 1][(j & 1) * 2]);
    }
}

// ---------------------------------------------------------------------------
// Pipelined GEMM core: acc += A[128,256] @ B[128,256]^T -> D 128x128.
// Double-buffered cp.async; ONE __syncthreads per iteration.
// ---------------------------------------------------------------------------
__device__ __forceinline__ void gemm_core(const __nv_bfloat16* __restrict__ A,
                                          int lda,
                                          const __nv_bfloat16* __restrict__ Bm,
                                          int ldb,
                                          float acc[2][8][4], uint32_t su) {
    const int tid  = threadIdx.x;
    const int warp = tid >> 5, lane = tid & 31;
    const int wm = warp >> 1, wn = warp & 1;        // 4x2 warp grid
    const int g  = lane >> 3, lr = lane & 7;

    const uint32_t xmask = (uint32_t)lr << 4;
    const uint32_t aoff  = (uint32_t)((wm * 32 + ((g & 1) << 3) + lr) << 7);
    const uint32_t acol  = (uint32_t)((g >> 1) << 4);
    const uint32_t boff  = STG_A + (uint32_t)((wn * 64 + ((g >> 1) << 3) + lr) << 7);
    const uint32_t bcol  = (uint32_t)((g & 1) << 4);

    // prologue: chunk 0 -> stage 0
    load_chunk(A,  lda, su);
    load_chunk(Bm, ldb, su + STG_A);
    asm volatile("cp.async.commit_group;");

#pragma unroll
    for (int ks = 0; ks < 4; ks++) {
        asm volatile("cp.async.wait_group 0;");   // chunk ks resident
        __syncthreads();                          // all warps done with other stage
        if (ks < 3) {
            uint32_t nbuf = su + (uint32_t)(((ks + 1) & 1) * STG);
            load_chunk(A  + (ks + 1) * CH, lda, nbuf);
            load_chunk(Bm + (ks + 1) * CH, ldb, nbuf + STG_A);
            asm volatile("cp.async.commit_group;");
        }
        uint32_t sbuf = su + (uint32_t)((ks & 1) * STG);
        compute_chunk(acc, sbuf + aoff, sbuf + boff, acol, bcol, xmask);
    }
}

// ---------------------------------------------------------------------------
// Epilogue: acc -> bf16 GMEM 128x128 tile (row stride ldo).
// ---------------------------------------------------------------------------
__device__ __forceinline__ void epi_bf16(float acc[2][8][4],
                                         __nv_bfloat16* __restrict__ dst,
                                         int ldo) {
    const int tid = threadIdx.x;
    const int warp = tid >> 5, lane = tid & 31;
    const int wm = warp >> 1, wn = warp & 1;
    const int r0 = wm * 32 + (lane >> 2);
    const int c0 = wn * 64 + ((lane & 3) << 1);
#pragma unroll
    for (int i = 0; i < 2; i++) {
#pragma unroll
        for (int j = 0; j < 8; j++) {
            float* d = acc[i][j];
            int r = r0 + i * 16;
            int c = c0 + j * 8;
            uint32_t p0, p1;
            asm("cvt.rn.satfinite.bf16x2.f32 %0, %1, %2;"
                : "=r"(p0) : "f"(d[1]), "f"(d[0]));
            asm("cvt.rn.satfinite.bf16x2.f32 %0, %1, %2;"
                : "=r"(p1) : "f"(d[3]), "f"(d[2]));
            *(uint32_t*)(dst + (size_t)r * ldo + c)       = p0;
            *(uint32_t*)(dst + (size_t)(r + 8) * ldo + c) = p1;
        }
    }
}

// ---------------------------------------------------------------------------
// Epilogue for final output: out = acc*inv + bias + residual (all fp32).
// ---------------------------------------------------------------------------
__device__ __forceinline__ void epi_bn(float acc[2][8][4],
                                       const float* __restrict__ Qfb,
                                       float* __restrict__ outb, int m_base,
                                       const float* __restrict__ gamma,
                                       const float* __restrict__ beta,
                                       const float* __restrict__ mean,
                                       const float* __restrict__ var) {
    const int tid = threadIdx.x;
    const int warp = tid >> 5, lane = tid & 31;
    const int wm = warp >> 1, wn = warp & 1;
    const int r0 = wm * 32 + (lane >> 2);
    const int c0 = wn * 64 + ((lane & 3) << 1);
#pragma unroll
    for (int i = 0; i < 2; i++) {
        int r = r0 + i * 16;
#pragma unroll
        for (int half = 0; half < 2; half++) {
            int rr = r + half * 8;
            int gidx = m_base + rr;
            float inv  = gamma[gidx] * rsqrtf(var[gidx] + EPS_BN);
            float bias = beta[gidx] - mean[gidx] * inv;
#pragma unroll
            for (int j = 0; j < 8; j++) {
                int c = c0 + j * 8;
                float d0 = acc[i][j][half * 2];
                float d1 = acc[i][j][half * 2 + 1];
                float2 rq = *(const float2*)(Qfb + (size_t)rr * NN + c);
                float2 o;
                o.x = d0 * inv + bias + rq.x;
                o.y = d1 * inv + bias + rq.y;
                *(float2*)(outb + (size_t)rr * NN + c) = o;
            }
        }
    }
}

#define ZERO_ACC(acc)                                                         \
    do {                                                                      \
        _Pragma("unroll") for (int _i = 0; _i < 2; _i++)                      \
        _Pragma("unroll") for (int _j = 0; _j < 8; _j++)                      \
        _Pragma("unroll") for (int _q = 0; _q < 4; _q++)                      \
            acc[_i][_j][_q] = 0.f;                                            \
    } while (0)

// ---------------------------------------------------------------------------
// Kernel: transpose+convert inputs [b][c][n] f32 -> [b][n][c] bf16 (z<16),
// plus weight conversion folded in (z==16). 64x64 tiles, vectorized I/O.
// grid (36, 4, 17), block 256.
// ---------------------------------------------------------------------------
__global__ void k_convx(const float* __restrict__ Qf, const float* __restrict__ KVf,
                        const float* __restrict__ Wq, const float* __restrict__ Wk,
                        const float* __restrict__ Wv, const float* __restrict__ Wz) {
    int z = blockIdx.z;
    int tid = threadIdx.x;
    if (z == 16) {
        // 4 weight matrices: 262144 elements over 32x4 blocks x 256 thr x 8
        int bx = blockIdx.x, by = blockIdx.y;
        if (bx < 32) {
            int base = (bx * 4 + by) * 256 + tid;
#pragma unroll
            for (int k = 0; k < 8; k++) {
                int i = base + k * 32768;
                int which = i >> 16, r = i & 65535;
                const float* src = (which == 0) ? Wq : (which == 1) ? Wk
                                  : (which == 2) ? Wv : Wz;
                __nv_bfloat16* dst = (which == 0) ? g_Wqb : (which == 1) ? g_Wkb
                                    : (which == 2) ? g_Wvb : g_Wzb;
                dst[r] = __float2bfloat16(src[r]);
            }
        }
        return;
    }
    __shared__ __nv_bfloat16 s[64][68];
    int b = z >> 1, sel = z & 1;
    const float* src = (sel ? KVf : Qf) + (size_t)b * Cc * NN;
    __nv_bfloat16* dst = (sel ? g_Xkv : g_Xq) + (size_t)b * NN * Cc;
    int n0 = blockIdx.x * 64, c0 = blockIdx.y * 64;
#pragma unroll
    for (int it = 0; it < 4; it++) {
        int idx = it * 256 + tid;
        int row = idx >> 4, q = idx & 15;   // row = c-rel, q = float4 along n
        float4 v = *(const float4*)(src + (size_t)(c0 + row) * NN + n0 + q * 4);
        s[row][q * 4 + 0] = __float2bfloat16(v.x);
        s[row][q * 4 + 1] = __float2bfloat16(v.y);
        s[row][q * 4 + 2] = __float2bfloat16(v.z);
        s[row][q * 4 + 3] = __float2bfloat16(v.w);
    }
    __syncthreads();
#pragma unroll
    for (int it = 0; it < 2; it++) {
        int idx = it * 256 + tid;
        int n = idx >> 3, c8 = idx & 7;     // 8 lanes cover 128B dst row chunk
        __nv_bfloat16 tmp[8];
#pragma unroll
        for (int j = 0; j < 8; j++) tmp[j] = s[c8 * 8 + j][n];
        *(uint4*)(dst + (size_t)(n0 + n) * Cc + c0 + c8 * 8) = *(uint4*)tmp;
    }
}

// ---------------------------------------------------------------------------
// GEMM kernels (all D tiles 128x128)
// ---------------------------------------------------------------------------
// Merged QKV.  grid 864: 0..575 K/V (channel-major out), 576..863 Q^T.
__global__ __launch_bounds__(NT, 2) void k_gemm1() {
    extern __shared__ char sm[];
    uint32_t su = s2u(sm);
    int id = blockIdx.x;
    const __nv_bfloat16 *A, *Bm;
    __nv_bfloat16* dst;
    int ldo;
    if (id < 576) {
        int b = id / 72, r = id % 72;
        int wsel = r / 36, r2 = r % 36, mt = r2 / 18, s = r2 % 18;
        A   = (wsel ? g_Wvb : g_Wkb) + mt * 128 * Cc;
        Bm  = g_Xkv + (size_t)b * NN * Cc + (size_t)s * 128 * Cc;
        dst = (wsel ? g_V : g_K) + (size_t)b * Cc * NN
              + (size_t)(mt * 128) * NN + s * 128;
        ldo = NN;
    } else {
        int id2 = id - 576;
        int b = id2 / 36, r = id2 % 36, mt = r / 2, nt = r & 1;
        A   = g_Xq + (size_t)b * NN * Cc + (size_t)mt * 128 * Cc;
        Bm  = g_Wqb + nt * 128 * Cc;
        dst = g_Qt + (size_t)b * NN * Cc + (size_t)mt * 128 * Cc + nt * 128;
        ldo = Cc;
    }
    float acc[2][8][4];
    ZERO_ACC(acc);
    gemm_core(A, Cc, Bm, Cc, acc, su);
    epi_bf16(acc, dst, ldo);
}

// KV partials = K @ V^T over 256-wide spatial chunks.  grid 288
__global__ __launch_bounds__(NT, 2) void k_gemm2() {
    extern __shared__ char sm[];
    uint32_t su = s2u(sm);
    int id = blockIdx.x;
    int b = id / 36, r = id % 36;
    int mt = r / 18, r3 = r % 18, nt = r3 / 9, s = r3 % 9;
    const __nv_bfloat16* A  = g_K + (size_t)b * Cc * NN + (size_t)(mt * 128) * NN + s * 256;
    const __nv_bfloat16* Bm = g_V + (size_t)b * Cc * NN + (size_t)(nt * 128) * NN + s * 256;
    __nv_bfloat16* dst = g_KVp + ((size_t)(b * NSPLIT + s) << 16)
                         + (size_t)(mt * 128) * Cc + nt * 128;
    float acc[2][8][4];
    ZERO_ACC(acc);
    gemm_core(A, NN, Bm, NN, acc, su);
    epi_bf16(acc, dst, Cc);
}

// ---------------------------------------------------------------------------
// M = Wz @ KV^T with the split-K reduction fused into the B-tile load:
// B[row,col] = bf16( (1/N) * sum_p KVp[p][row,col] )  — bit-identical to the
// old k_reduce + cp.async path. B tile (128x256, all 4 chunks) resident at
// su+32768; A double-buffered at su+0/su+16384.  grid 32.
// ---------------------------------------------------------------------------
__global__ __launch_bounds__(NT, 2) void k_gemm3() {
    extern __shared__ char sm[];
    uint32_t su = s2u(sm);
    const int tid = threadIdx.x;
    int id = blockIdx.x;
    int b = id / 4, r = id % 4, mt = r >> 1, nt = r & 1;
    const __nv_bfloat16* A = g_Wzb + mt * 128 * Cc;
    __nv_bfloat16* dst = g_M + ((size_t)b << 16) + (size_t)(mt * 128) * Cc + nt * 128;

    // ---- B fill: sum 9 partials in fp32, scale 1/N, convert, swizzle ----
    {
        const size_t pbase = ((size_t)(b * NSPLIT) << 16) + (size_t)(nt * 128) * Cc;
#pragma unroll
        for (int it = 0; it < 16; it++) {
            int pos = it * NT + tid;
            int row = pos >> 5, cb = pos & 31;    // row 0..127, cb = 8-elem block
            float s8[8];
#pragma unroll
            for (int j = 0; j < 8; j++) s8[j] = 0.f;
#pragma unroll
            for (int p = 0; p < NSPLIT; p++) {
                uint4 v = *(const uint4*)&g_KVp[pbase + ((size_t)p << 16)
                                                + (size_t)row * Cc + cb * 8];
                const __nv_bfloat16* h = (const __nv_bfloat16*)&v;
#pragma unroll
                for (int j = 0; j < 8; j++) s8[j] += __bfloat162float(h[j]);
            }
            __nv_bfloat16 o[8];
#pragma unroll
            for (int j = 0; j < 8; j++)
                o[j] = __float2bfloat16(s8[j] * (1.0f / (float)NN));
            int ks = cb >> 3, c16 = cb & 7;
            uint32_t phys = 32768u + (uint32_t)ks * 16384u + ((uint32_t)row << 7)
                          + (((uint32_t)c16 ^ ((uint32_t)row & 7u)) << 4);
            *(uint4*)(sm + phys) = *(uint4*)o;
        }
    }

    // ---- A pipeline + compute ----
    float acc[2][8][4];
    ZERO_ACC(acc);
    const int warp = tid >> 5, lane = tid & 31;
    const int wm = warp >> 1, wn = warp & 1;
    const int g = lane >> 3, lr = lane & 7;
    const uint32_t xmask = (uint32_t)lr << 4;
    const uint32_t aoff  = (uint32_t)((wm * 32 + ((g & 1) << 3) + lr) << 7);
    const uint32_t acol  = (uint32_t)((g >> 1) << 4);
    const uint32_t boffw = (uint32_t)((wn * 64 + ((g >> 1) << 3) + lr) << 7);
    const uint32_t bcol  = (uint32_t)((g & 1) << 4);

    load_chunk(A, Cc, su);
    asm volatile("cp.async.commit_group;");

#pragma unroll
    for (int ks = 0; ks < 4; ks++) {
        asm volatile("cp.async.wait_group 0;");
        __syncthreads();            // (first iter also publishes the B fill)
        if (ks < 3) {
            load_chunk(A + (ks + 1) * CH, Cc, su + (uint32_t)(((ks + 1) & 1) * 16384));
            asm volatile("cp.async.commit_group;");
        }
        compute_chunk(acc,
                      su + (uint32_t)((ks & 1) * 16384) + aoff,
                      su + 32768u + (uint32_t)ks * 16384u + boffw,
                      acol, bcol, xmask);
    }
    epi_bf16(acc, dst, Cc);
}

// out = (M @ Q) * inv + bias + residual.  grid 288
__global__ __launch_bounds__(NT, 2) void k_gemm4(const float* __restrict__ Qf,
                                                 const float* __restrict__ gamma,
                                                 const float* __restrict__ beta,
                                                 const float* __restrict__ mean,
                                                 const float* __restrict__ var,
                                                 float* __restrict__ out) {
    extern __shared__ char sm[];
    uint32_t su = s2u(sm);
    int id = blockIdx.x;
    int b = id / 36, r = id % 36, mt = r / 18, s = r % 18;
    const __nv_bfloat16* A  = g_M + ((size_t)b << 16) + (size_t)(mt * 128) * Cc;
    const __nv_bfloat16* Bm = g_Qt + (size_t)b * NN * Cc + (size_t)s * 128 * Cc;
    size_t off = (size_t)b * Cc * NN + (size_t)(mt * 128) * NN + s * 128;
    float acc[2][8][4];
    ZERO_ACC(acc);
    gemm_core(A, Cc, Bm, Cc, acc, su);
    epi_bn(acc, Qf + off, out + off, mt * 128, gamma, beta, mean, var);
}

// ---------------------------------------------------------------------------
// Launch
// ---------------------------------------------------------------------------
extern "C" void kernel_launch(void* const* d_in, const int* in_sizes, int n_in,
                              void* d_out, int out_size) {
    const float* Qf    = (const float*)d_in[0];
    const float* KVf   = (const float*)d_in[1];
    const float* Wq    = (const float*)d_in[2];
    const float* Wk    = (const float*)d_in[3];
    const float* Wv    = (const float*)d_in[4];
    const float* Wz    = (const float*)d_in[5];
    const float* gamma = (const float*)d_in[6];
    const float* beta  = (const float*)d_in[7];
    const float* mean  = (const float*)d_in[8];
    const float* var   = (const float*)d_in[9];
    float* out = (float*)d_out;

    cudaFuncSetAttribute(k_gemm1, cudaFuncAttributeMaxDynamicSharedMemorySize, SMEM_TOTAL);
    cudaFuncSetAttribute(k_gemm2, cudaFuncAttributeMaxDynamicSharedMemorySize, SMEM_TOTAL);
    cudaFuncSetAttribute(k_gemm3, cudaFuncAttributeMaxDynamicSharedMemorySize, SMEM_G3);
    cudaFuncSetAttribute(k_gemm4, cudaFuncAttributeMaxDynamicSharedMemorySize, SMEM_TOTAL);

    k_convx<<<dim3(NN / 64, Cc / 64, Bb * 2 + 1), 256>>>(Qf, KVf, Wq, Wk, Wv, Wz);
    k_gemm1<<<864, NT, SMEM_TOTAL>>>();
    k_gemm2<<<288, NT, SMEM_TOTAL>>>();
    k_gemm3<<<32, NT, SMEM_G3>>>();
    k_gemm4<<<288, NT, SMEM_TOTAL>>>(Qf, gamma, beta, mean, var, out);
}

// round 16
// speedup vs baseline: 1.0298x; 1.0298x over previous
#include <cuda_runtime.h>
#include <cuda_bf16.h>
#include <cstdint>

// ---------------------------------------------------------------------------
// Problem constants
// ---------------------------------------------------------------------------
#define Bb 8
#define Cc 256
#define NN 2304
#define EPS_BN 1e-5f
#define NSPLIT 9                 // spatial split for K@V^T (2304 / 256)

#define CH 64                    // K-chunk width (elements)
#define STG_A (128 * 128)        // A chunk bytes: 128 rows x 128B
#define STG_B (128 * 128)        // B chunk bytes: 128 rows x 128B
#define STG (STG_A + STG_B)      // 32768 per stage
#define SMEM_TOTAL (2 * STG)     // 65536 (double buffered) -> 2 CTAs/SM

#define NT 256                   // threads per GEMM CTA (8 warps, 4x2 grid)

// ---------------------------------------------------------------------------
// Scratch (static device globals)
// ---------------------------------------------------------------------------
__device__ __nv_bfloat16 g_Xq [Bb * NN * Cc];   // Q_feat transposed [b][n][c]
__device__ __nv_bfloat16 g_Xkv[Bb * NN * Cc];   // KV_feat transposed [b][n][c]
__device__ __nv_bfloat16 g_Qt [Bb * NN * Cc];   // Q   in [b][n][o]
__device__ __nv_bfloat16 g_K  [Bb * Cc * NN];   // K   in [b][o][n]
__device__ __nv_bfloat16 g_V  [Bb * Cc * NN];   // V   in [b][o][n]
__device__ __nv_bfloat16 g_KVp[Bb * NSPLIT * Cc * Cc]; // K@V^T split partials
__device__ __nv_bfloat16 g_KV [Bb * Cc * Cc];   // reduced, /N
__device__ __nv_bfloat16 g_M  [Bb * Cc * Cc];   // Wz @ KV^T  [b][o][c]
__device__ __nv_bfloat16 g_Wqb[Cc * Cc];
__device__ __nv_bfloat16 g_Wkb[Cc * Cc];
__device__ __nv_bfloat16 g_Wvb[Cc * Cc];
__device__ __nv_bfloat16 g_Wzb[Cc * Cc];

// ---------------------------------------------------------------------------
// PTX helpers (baseline ISA only; no sm_103a-accelerated features)
// ---------------------------------------------------------------------------
__device__ __forceinline__ uint32_t s2u(const void* p) {
    uint32_t a;
    asm("{ .reg .u64 t; cvta.to.shared.u64 t, %1; cvt.u32.u64 %0, t; }"
        : "=r"(a) : "l"(p));
    return a;
}

__device__ __forceinline__ void ldsm4(uint32_t* r, uint32_t addr) {
    asm volatile(
        "ldmatrix.sync.aligned.m8n8.x4.shared.b16 {%0,%1,%2,%3}, [%4];"
        : "=r"(r[0]), "=r"(r[1]), "=r"(r[2]), "=r"(r[3]) : "r"(addr));
}

__device__ __forceinline__ void mma16816(float* d, const uint32_t* a,
                                         const uint32_t* b) {
    asm volatile(
        "mma.sync.aligned.m16n8k16.row.col.f32.bf16.bf16.f32 "
        "{%0,%1,%2,%3}, {%4,%5,%6,%7}, {%8,%9}, {%0,%1,%2,%3};"
        : "+f"(d[0]), "+f"(d[1]), "+f"(d[2]), "+f"(d[3])
        : "r"(a[0]), "r"(a[1]), "r"(a[2]), "r"(a[3]), "r"(b[0]), "r"(b[1]));
}

__device__ __forceinline__ void cp16(uint32_t dst, const void* src) {
    asm volatile("cp.async.cg.shared.global [%0], [%1], 16;"
                 :: "r"(dst), "l"(src));
}

// ---------------------------------------------------------------------------
// Async chunk loader: GMEM [128 rows x 64 bf16, row stride ld] -> swizzled
// SMEM stage. Row = 128B (8 x 16B chunks), chunk index XOR (row & 7).
// ---------------------------------------------------------------------------
__device__ __forceinline__ void load_chunk(const __nv_bfloat16* __restrict__ src,
                                           int ld, uint32_t dstu) {
    const int tid = threadIdx.x;
#pragma unroll
    for (int it = 0; it < 4; it++) {     // 128*8 chunks / 256 threads
        int idx = it * NT + tid;
        int row = idx >> 3;
        int c16 = idx & 7;
        uint32_t phys = ((uint32_t)row << 7) +
                        (((uint32_t)c16 ^ ((uint32_t)row & 7u)) << 4);
        cp16(dstu + phys, src + (size_t)row * ld + c16 * 8);
    }
}

// ---------------------------------------------------------------------------
// Compute one 64-wide k-chunk: acc[2][8][4] += A_chunk @ B_chunk^T
// 8 warps (4x2); warp (wm,wn) owns 32x64 of the 128x128 D tile.
// ---------------------------------------------------------------------------
__device__ __forceinline__ void compute_chunk(float acc[2][8][4],
                                              uint32_t abase, uint32_t bbase,
                                              uint32_t acol, uint32_t bcol,
                                              uint32_t xmask) {
#pragma unroll
    for (int k2 = 0; k2 < 4; k2++) {
        const uint32_t kb = (uint32_t)(k2 << 5);
        uint32_t a[2][4];
#pragma unroll
        for (int i = 0; i < 2; i++)
            ldsm4(a[i], abase + (uint32_t)(i << 11) + ((acol + kb) ^ xmask));
        uint32_t b[4][4];
#pragma unroll
        for (int jp = 0; jp < 4; jp++)
            ldsm4(b[jp], bbase + (uint32_t)(jp << 11) + ((bcol + kb) ^ xmask));
#pragma unroll
        for (int i = 0; i < 2; i++)
#pragma unroll
            for (int j = 0; j < 8; j++)
                mma16816(acc[i][j], a[i], &b[j >> 1][(j & 1) * 2]);
    }
}

// ---------------------------------------------------------------------------
// Pipelined GEMM core: acc += A[128,256] @ B[128,256]^T -> D 128x128.
// Double-buffered cp.async; ONE __syncthreads per iteration.
// ---------------------------------------------------------------------------
__device__ __forceinline__ void gemm_core(const __nv_bfloat16* __restrict__ A,
                                          int lda,
                                          const __nv_bfloat16* __restrict__ Bm,
                                          int ldb,
                                          float acc[2][8][4], uint32_t su) {
    const int tid  = threadIdx.x;
    const int warp = tid >> 5, lane = tid & 31;
    const int wm = warp >> 1, wn = warp & 1;        // 4x2 warp grid
    const int g  = lane >> 3, lr = lane & 7;

    const uint32_t xmask = (uint32_t)lr << 4;
    const uint32_t aoff  = (uint32_t)((wm * 32 + ((g & 1) << 3) + lr) << 7);
    const uint32_t acol  = (uint32_t)((g >> 1) << 4);
    const uint32_t boff  = STG_A + (uint32_t)((wn * 64 + ((g >> 1) << 3) + lr) << 7);
    const uint32_t bcol  = (uint32_t)((g & 1) << 4);

    // prologue: chunk 0 -> stage 0
    load_chunk(A,  lda, su);
    load_chunk(Bm, ldb, su + STG_A);
    asm volatile("cp.async.commit_group;");

#pragma unroll
    for (int ks = 0; ks < 4; ks++) {
        asm volatile("cp.async.wait_group 0;");   // chunk ks resident
        __syncthreads();                          // all warps done with other stage
        if (ks < 3) {
            uint32_t nbuf = su + (uint32_t)(((ks + 1) & 1) * STG);
            load_chunk(A  + (ks + 1) * CH, lda, nbuf);
            load_chunk(Bm + (ks + 1) * CH, ldb, nbuf + STG_A);
            asm volatile("cp.async.commit_group;");
        }
        uint32_t sbuf = su + (uint32_t)((ks & 1) * STG);
        compute_chunk(acc, sbuf + aoff, sbuf + boff, acol, bcol, xmask);
    }
}

// ---------------------------------------------------------------------------
// Epilogue: acc -> bf16 GMEM 128x128 tile (row stride ldo).
// ---------------------------------------------------------------------------
__device__ __forceinline__ void epi_bf16(float acc[2][8][4],
                                         __nv_bfloat16* __restrict__ dst,
                                         int ldo) {
    const int tid = threadIdx.x;
    const int warp = tid >> 5, lane = tid & 31;
    const int wm = warp >> 1, wn = warp & 1;
    const int r0 = wm * 32 + (lane >> 2);
    const int c0 = wn * 64 + ((lane & 3) << 1);
#pragma unroll
    for (int i = 0; i < 2; i++) {
#pragma unroll
        for (int j = 0; j < 8; j++) {
            float* d = acc[i][j];
            int r = r0 + i * 16;
            int c = c0 + j * 8;
            uint32_t p0, p1;
            asm("cvt.rn.satfinite.bf16x2.f32 %0, %1, %2;"
                : "=r"(p0) : "f"(d[1]), "f"(d[0]));
            asm("cvt.rn.satfinite.bf16x2.f32 %0, %1, %2;"
                : "=r"(p1) : "f"(d[3]), "f"(d[2]));
            *(uint32_t*)(dst + (size_t)r * ldo + c)       = p0;
            *(uint32_t*)(dst + (size_t)(r + 8) * ldo + c) = p1;
        }
    }
}

// ---------------------------------------------------------------------------
// Epilogue for final output: out = acc*inv + bias + residual (all fp32).
// ---------------------------------------------------------------------------
__device__ __forceinline__ void epi_bn(float acc[2][8][4],
                                       const float* __restrict__ Qfb,
                                       float* __restrict__ outb, int m_base,
                                       const float* __restrict__ gamma,
                                       const float* __restrict__ beta,
                                       const float* __restrict__ mean,
                                       const float* __restrict__ var) {
    const int tid = threadIdx.x;
    const int warp = tid >> 5, lane = tid & 31;
    const int wm = warp >> 1, wn = warp & 1;
    const int r0 = wm * 32 + (lane >> 2);
    const int c0 = wn * 64 + ((lane & 3) << 1);
#pragma unroll
    for (int i = 0; i < 2; i++) {
        int r = r0 + i * 16;
#pragma unroll
        for (int half = 0; half < 2; half++) {
            int rr = r + half * 8;
            int gidx = m_base + rr;
            float inv  = gamma[gidx] * rsqrtf(var[gidx] + EPS_BN);
            float bias = beta[gidx] - mean[gidx] * inv;
#pragma unroll
            for (int j = 0; j < 8; j++) {
                int c = c0 + j * 8;
                float d0 = acc[i][j][half * 2];
                float d1 = acc[i][j][half * 2 + 1];
                float2 rq = *(const float2*)(Qfb + (size_t)rr * NN + c);
                float2 o;
                o.x = d0 * inv + bias + rq.x;
                o.y = d1 * inv + bias + rq.y;
                *(float2*)(outb + (size_t)rr * NN + c) = o;
            }
        }
    }
}

#define ZERO_ACC(acc)                                                         \
    do {                                                                      \
        _Pragma("unroll") for (int _i = 0; _i < 2; _i++)                      \
        _Pragma("unroll") for (int _j = 0; _j < 8; _j++)                      \
        _Pragma("unroll") for (int _q = 0; _q < 4; _q++)                      \
            acc[_i][_j][_q] = 0.f;                                            \
    } while (0)

// ---------------------------------------------------------------------------
// Kernel: transpose+convert inputs [b][c][n] f32 -> [b][n][c] bf16 (z<16),
// plus weight conversion folded in (z==16). 64x64 tiles, vectorized I/O.
// grid (36, 4, 17), block 256.
// ---------------------------------------------------------------------------
__global__ void k_convx(const float* __restrict__ Qf, const float* __restrict__ KVf,
                        const float* __restrict__ Wq, const float* __restrict__ Wk,
                        const float* __restrict__ Wv, const float* __restrict__ Wz) {
    int z = blockIdx.z;
    int tid = threadIdx.x;
    if (z == 16) {
        int bx = blockIdx.x, by = blockIdx.y;
        if (bx < 32) {
            int base = (bx * 4 + by) * 256 + tid;
#pragma unroll
            for (int k = 0; k < 8; k++) {
                int i = base + k * 32768;
                int which = i >> 16, r = i & 65535;
                const float* src = (which == 0) ? Wq : (which == 1) ? Wk
                                  : (which == 2) ? Wv : Wz;
                __nv_bfloat16* dst = (which == 0) ? g_Wqb : (which == 1) ? g_Wkb
                                    : (which == 2) ? g_Wvb : g_Wzb;
                dst[r] = __float2bfloat16(src[r]);
            }
        }
        return;
    }
    __shared__ __nv_bfloat16 s[64][68];
    int b = z >> 1, sel = z & 1;
    const float* src = (sel ? KVf : Qf) + (size_t)b * Cc * NN;
    __nv_bfloat16* dst = (sel ? g_Xkv : g_Xq) + (size_t)b * NN * Cc;
    int n0 = blockIdx.x * 64, c0 = blockIdx.y * 64;
#pragma unroll
    for (int it = 0; it < 4; it++) {
        int idx = it * 256 + tid;
        int row = idx >> 4, q = idx & 15;
        float4 v = *(const float4*)(src + (size_t)(c0 + row) * NN + n0 + q * 4);
        s[row][q * 4 + 0] = __float2bfloat16(v.x);
        s[row][q * 4 + 1] = __float2bfloat16(v.y);
        s[row][q * 4 + 2] = __float2bfloat16(v.z);
        s[row][q * 4 + 3] = __float2bfloat16(v.w);
    }
    __syncthreads();
#pragma unroll
    for (int it = 0; it < 2; it++) {
        int idx = it * 256 + tid;
        int n = idx >> 3, c8 = idx & 7;
        __nv_bfloat16 tmp[8];
#pragma unroll
        for (int j = 0; j < 8; j++) tmp[j] = s[c8 * 8 + j][n];
        *(uint4*)(dst + (size_t)(n0 + n) * Cc + c0 + c8 * 8) = *(uint4*)tmp;
    }
}

// ---------------------------------------------------------------------------
// GEMM kernels (all D tiles 128x128)
// ---------------------------------------------------------------------------
// Merged QKV.  grid 864: 0..575 K/V (channel-major out), 576..863 Q^T.
__global__ __launch_bounds__(NT, 2) void k_gemm1() {
    extern __shared__ char sm[];
    uint32_t su = s2u(sm);
    int id = blockIdx.x;
    const __nv_bfloat16 *A, *Bm;
    __nv_bfloat16* dst;
    int ldo;
    if (id < 576) {
        int b = id / 72, r = id % 72;
        int wsel = r / 36, r2 = r % 36, mt = r2 / 18, s = r2 % 18;
        A   = (wsel ? g_Wvb : g_Wkb) + mt * 128 * Cc;
        Bm  = g_Xkv + (size_t)b * NN * Cc + (size_t)s * 128 * Cc;
        dst = (wsel ? g_V : g_K) + (size_t)b * Cc * NN
              + (size_t)(mt * 128) * NN + s * 128;
        ldo = NN;
    } else {
        int id2 = id - 576;
        int b = id2 / 36, r = id2 % 36, mt = r / 2, nt = r & 1;
        A   = g_Xq + (size_t)b * NN * Cc + (size_t)mt * 128 * Cc;
        Bm  = g_Wqb + nt * 128 * Cc;
        dst = g_Qt + (size_t)b * NN * Cc + (size_t)mt * 128 * Cc + nt * 128;
        ldo = Cc;
    }
    float acc[2][8][4];
    ZERO_ACC(acc);
    gemm_core(A, Cc, Bm, Cc, acc, su);
    epi_bf16(acc, dst, ldo);
}

// KV partials = K @ V^T over 256-wide spatial chunks.  grid 288
__global__ __launch_bounds__(NT, 2) void k_gemm2() {
    extern __shared__ char sm[];
    uint32_t su = s2u(sm);
    int id = blockIdx.x;
    int b = id / 36, r = id % 36;
    int mt = r / 18, r3 = r % 18, nt = r3 / 9, s = r3 % 9;
    const __nv_bfloat16* A  = g_K + (size_t)b * Cc * NN + (size_t)(mt * 128) * NN + s * 256;
    const __nv_bfloat16* Bm = g_V + (size_t)b * Cc * NN + (size_t)(nt * 128) * NN + s * 256;
    __nv_bfloat16* dst = g_KVp + ((size_t)(b * NSPLIT + s) << 16)
                         + (size_t)(mt * 128) * Cc + nt * 128;
    float acc[2][8][4];
    ZERO_ACC(acc);
    gemm_core(A, NN, Bm, NN, acc, su);
    epi_bf16(acc, dst, Cc);
}

// Reduce partials, scale by 1/N. 4 elems/thread via uint2, grid 512 -> 2x the
// concurrency of the R10 version (DRAM-latency bound).
__global__ void k_reduce() {
    int t = blockIdx.x * 256 + threadIdx.x;
    int i = t * 4;
    int b = i >> 16, r = i & 65535;
    float sum[4];
#pragma unroll
    for (int j = 0; j < 4; j++) sum[j] = 0.f;
#pragma unroll
    for (int p = 0; p < NSPLIT; p++) {
        uint2 v = *(const uint2*)&g_KVp[((size_t)(b * NSPLIT + p) << 16) + r];
        const __nv_bfloat16* h = (const __nv_bfloat16*)&v;
#pragma unroll
        for (int j = 0; j < 4; j++) sum[j] += __bfloat162float(h[j]);
    }
    __nv_bfloat16 o[4];
#pragma unroll
    for (int j = 0; j < 4; j++)
        o[j] = __float2bfloat16(sum[j] * (1.0f / (float)NN));
    *(uint2*)&g_KV[i] = *(uint2*)o;
}

// M = Wz @ KV^T.  grid 32
__global__ __launch_bounds__(NT, 2) void k_gemm3() {
    extern __shared__ char sm[];
    uint32_t su = s2u(sm);
    int id = blockIdx.x;
    int b = id / 4, r = id % 4, mt = r >> 1, nt = r & 1;
    const __nv_bfloat16* A  = g_Wzb + mt * 128 * Cc;
    const __nv_bfloat16* Bm = g_KV + ((size_t)b << 16) + (size_t)(nt * 128) * Cc;
    __nv_bfloat16* dst = g_M + ((size_t)b << 16) + (size_t)(mt * 128) * Cc + nt * 128;
    float acc[2][8][4];
    ZERO_ACC(acc);
    gemm_core(A, Cc, Bm, Cc, acc, su);
    epi_bf16(acc, dst, Cc);
}

// out = (M @ Q) * inv + bias + residual.  grid 288
__global__ __launch_bounds__(NT, 2) void k_gemm4(const float* __restrict__ Qf,
                                                 const float* __restrict__ gamma,
                                                 const float* __restrict__ beta,
                                                 const float* __restrict__ mean,
                                                 const float* __restrict__ var,
                                                 float* __restrict__ out) {
    extern __shared__ char sm[];
    uint32_t su = s2u(sm);
    int id = blockIdx.x;
    int b = id / 36, r = id % 36, mt = r / 18, s = r % 18;
    const __nv_bfloat16* A  = g_M + ((size_t)b << 16) + (size_t)(mt * 128) * Cc;
    const __nv_bfloat16* Bm = g_Qt + (size_t)b * NN * Cc + (size_t)s * 128 * Cc;
    size_t off = (size_t)b * Cc * NN + (size_t)(mt * 128) * NN + s * 128;
    float acc[2][8][4];
    ZERO_ACC(acc);
    gemm_core(A, Cc, Bm, Cc, acc, su);
    epi_bn(acc, Qf + off, out + off, mt * 128, gamma, beta, mean, var);
}

// ---------------------------------------------------------------------------
// Launch
// ---------------------------------------------------------------------------
extern "C" void kernel_launch(void* const* d_in, const int* in_sizes, int n_in,
                              void* d_out, int out_size) {
    const float* Qf    = (const float*)d_in[0];
    const float* KVf   = (const float*)d_in[1];
    const float* Wq    = (const float*)d_in[2];
    const float* Wk    = (const float*)d_in[3];
    const float* Wv    = (const float*)d_in[4];
    const float* Wz    = (const float*)d_in[5];
    const float* gamma = (const float*)d_in[6];
    const float* beta  = (const float*)d_in[7];
    const float* mean  = (const float*)d_in[8];
    const float* var   = (const float*)d_in[9];
    float* out = (float*)d_out;

    cudaFuncSetAttribute(k_gemm1, cudaFuncAttributeMaxDynamicSharedMemorySize, SMEM_TOTAL);
    cudaFuncSetAttribute(k_gemm2, cudaFuncAttributeMaxDynamicSharedMemorySize, SMEM_TOTAL);
    cudaFuncSetAttribute(k_gemm3, cudaFuncAttributeMaxDynamicSharedMemorySize, SMEM_TOTAL);
    cudaFuncSetAttribute(k_gemm4, cudaFuncAttributeMaxDynamicSharedMemorySize, SMEM_TOTAL);

    k_convx<<<dim3(NN / 64, Cc / 64, Bb * 2 + 1), 256>>>(Qf, KVf, Wq, Wk, Wv, Wz);
    k_gemm1<<<864, NT, SMEM_TOTAL>>>();
    k_gemm2<<<288, NT, SMEM_TOTAL>>>();
    k_reduce<<<512, 256>>>();
    k_gemm3<<<32, NT, SMEM_TOTAL>>>();
    k_gemm4<<<288, NT, SMEM_TOTAL>>>(Qf, gamma, beta, mean, var, out);
}